// round 1
// baseline (speedup 1.0000x reference)
#include <cuda_runtime.h>

typedef unsigned long long u64;

#define IC 6
#define OC 16
#define HW 512
#define OHW 508
#define TW 32
#define TH 64
#define TILE_COLS 36
#define TILE_ROWS 68
#define RP 69   // padded row-pitch of transposed input tile (69 mod 32 = 5, coprime -> conflict-free)

__device__ __forceinline__ u64 pack2(float lo, float hi) {
    u64 r; asm("mov.b64 %0, {%1, %2};" : "=l"(r) : "f"(lo), "f"(hi)); return r;
}
__device__ __forceinline__ float2 unpack2(u64 v) {
    float2 f; asm("mov.b64 {%0, %1}, %2;" : "=f"(f.x), "=f"(f.y) : "l"(v)); return f;
}
// Blackwell packed dual-FMA: 2 fp32 FMAs per instruction (rt 2 -> 128 FMA/cyc/SM)
__device__ __forceinline__ u64 ffma2(u64 a, u64 b, u64 c) {
    u64 d; asm("fma.rn.f32x2 %0, %1, %2, %3;" : "=l"(d) : "l"(a), "l"(b), "l"(c)); return d;
}

// LeNet C3 connectivity, one 6-bit mask per output channel (compile-time).
__device__ __forceinline__ constexpr unsigned conn_bits(int oc) {
    switch (oc) {
        case 0:  return 0x07u; case 1:  return 0x0Eu; case 2:  return 0x1Cu; case 3:  return 0x38u;
        case 4:  return 0x31u; case 5:  return 0x23u; case 6:  return 0x0Fu; case 7:  return 0x1Eu;
        case 8:  return 0x3Cu; case 9:  return 0x39u; case 10: return 0x33u; case 11: return 0x27u;
        case 12: return 0x1Bu; case 13: return 0x36u; case 14: return 0x2Du; case 15: return 0x3Fu;
    }
    return 0u;
}

extern __shared__ unsigned char smem_raw[];

__global__ __launch_bounds__(256)
void c3_kernel(const float* __restrict__ x, const float* __restrict__ w,
               const float* __restrict__ bias, float* __restrict__ out)
{
    u64*   sW2 = (u64*)smem_raw;                        // 16*6*25 packed (w,w): 19200 B
    float* sin = (float*)(smem_raw + OC * IC * 25 * 8); // transposed tile [ic][col(36)][row(69 pitch)]

    const int tid = threadIdx.x;
    const int tx = tid & 31, ty = tid >> 5;
    const int gx0 = blockIdx.x * TW, gy0 = blockIdx.y * TH;
    const int b = blockIdx.z;

    // Stage weights, duplicated into f32x2 lanes (broadcast-friendly LDS.64 later).
    for (int i = tid; i < OC * IC * 25; i += 256) {
        float wv = w[i];
        sW2[i] = pack2(wv, wv);
    }
    // Stage input tile transposed: vertical neighbors contiguous -> packed pairs cheap.
    for (int i = tid; i < IC * TILE_ROWS * TILE_COLS; i += 256) {
        int c  = i % TILE_COLS;
        int t2 = i / TILE_COLS;
        int r  = t2 % TILE_ROWS;
        int ic = t2 / TILE_ROWS;
        int gx = gx0 + c, gy = gy0 + r;
        float v = 0.f;
        if (gx < HW && gy < HW)
            v = x[(((size_t)b * IC + ic) * HW + gy) * HW + gx];
        sin[(ic * TILE_COLS + c) * RP + r] = v;
    }
    __syncthreads();

    const int  yb  = ty * 8;          // this thread's 8 output rows: yb..yb+7
    const int  ox  = gx0 + tx;
    const bool xok = ox < OHW;

    #pragma unroll
    for (int g = 0; g < 2; ++g) {     // two passes of 8 output channels, smem tile reused
        u64 acc[8][4];
        #pragma unroll
        for (int o = 0; o < 8; ++o)
            #pragma unroll
            for (int q = 0; q < 4; ++q) acc[o][q] = 0ULL;

        #pragma unroll
        for (int ic = 0; ic < IC; ++ic) {
            #pragma unroll
            for (int kx = 0; kx < 5; ++kx) {
                const float* col = &sin[(ic * TILE_COLS + tx + kx) * RP + yb];
                float v[12];
                #pragma unroll
                for (int r = 0; r < 12; ++r) v[r] = col[r];
                u64 p[11];                       // overlapping vertical pairs (r, r+1)
                #pragma unroll
                for (int r = 0; r < 11; ++r) p[r] = pack2(v[r], v[r + 1]);

                #pragma unroll
                for (int ky = 0; ky < 5; ++ky) {
                    #pragma unroll
                    for (int o = 0; o < 8; ++o) {
                        if ((conn_bits(g * 8 + o) >> ic) & 1u) {   // compile-time prune
                            u64 w2 = sW2[((g * 8 + o) * IC + ic) * 25 + ky * 5 + kx];
                            #pragma unroll
                            for (int q = 0; q < 4; ++q)
                                acc[o][q] = ffma2(p[2 * q + ky], w2, acc[o][q]);
                        }
                    }
                }
            }
        }

        #pragma unroll
        for (int o = 0; o < 8; ++o) {
            const int och = g * 8 + o;
            const float bv = __ldg(&bias[och]);
            float* obase = out + ((size_t)b * OC + och) * OHW * OHW;
            #pragma unroll
            for (int q = 0; q < 4; ++q) {
                float2 f = unpack2(acc[o][q]);
                int oy = gy0 + yb + 2 * q;
                if (xok) {
                    if (oy < OHW)     obase[(size_t)oy * OHW + ox]       = f.x + bv;
                    if (oy + 1 < OHW) obase[(size_t)(oy + 1) * OHW + ox] = f.y + bv;
                }
            }
        }
    }
}

extern "C" void kernel_launch(void* const* d_in, const int* in_sizes, int n_in,
                              void* d_out, int out_size)
{
    const float* x    = (const float*)d_in[0];
    const float* w    = (const float*)d_in[1];
    const float* bias = (const float*)d_in[2];
    float* out = (float*)d_out;

    const int smem = OC * IC * 25 * 8 + IC * TILE_COLS * RP * (int)sizeof(float); // 78816 B
    cudaFuncSetAttribute(c3_kernel, cudaFuncAttributeMaxDynamicSharedMemorySize, smem);

    dim3 grid((OHW + TW - 1) / TW, (OHW + TH - 1) / TH, 32);
    c3_kernel<<<grid, 256, smem>>>(x, w, bias, out);
}

// round 13
// speedup vs baseline: 1.4028x; 1.4028x over previous
#include <cuda_runtime.h>

typedef unsigned long long u64;

#define IC 6
#define OC 16
#define HW 512
#define OHW 508
#define TW 32        // output tile width  (== 32 lanes)
#define TH 32        // output tile height (8 warps * 4 rows)
#define RPT 4        // rows per thread
#define TCOLS 36     // input tile cols  (TW + 4)
#define TROWS 36     // input tile rows  (TH + 4)
#define RPITCH 37    // row pitch in u64 (lane stride 74 words -> conflict-free LDS.64 phases)

#define NW 900       // packed weights: 6 ic * 6 pairs * 25 taps
#define SW_BYTES 7232                       // 900*8 rounded up to 16
#define SIN_ELEMS (IC * TCOLS * RPITCH)     // u64 elements
#define SMEM_TOTAL (SW_BYTES + SIN_ELEMS * 8)

__device__ __forceinline__ u64 pack2(float lo, float hi) {
    u64 r; asm("mov.b64 %0, {%1, %2};" : "=l"(r) : "f"(lo), "f"(hi)); return r;
}
__device__ __forceinline__ float2 unpack2(u64 v) {
    float2 f; asm("mov.b64 {%0, %1}, %2;" : "=f"(f.x), "=f"(f.y) : "l"(v)); return f;
}
// Blackwell packed dual fp32 FMA (SASS FFMA2 via PTX only): 2 FMAs/instr.
__device__ __forceinline__ u64 ffma2(u64 a, u64 b, u64 c) {
    u64 d; asm("fma.rn.f32x2 %0, %1, %2, %3;" : "=l"(d) : "l"(a), "l"(b), "l"(c)); return d;
}

// LeNet C3 connectivity, one 6-bit mask per output channel. constexpr -> folds.
__host__ __device__ __forceinline__ constexpr unsigned conn_bits(int oc) {
    constexpr unsigned m[16] = {0x07u, 0x0Eu, 0x1Cu, 0x38u, 0x31u, 0x23u,
                                0x0Fu, 0x1Eu, 0x3Cu, 0x39u, 0x33u, 0x27u,
                                0x1Bu, 0x36u, 0x2Du, 0x3Fu};
    return m[oc];
}
// Output channels packed into 8 f32x2 pairs (max connectivity overlap).
__host__ __device__ __forceinline__ constexpr int pair_a(int p) {
    constexpr int t[8] = {0, 1, 2, 3, 4, 5, 12, 14}; return t[p];
}
__host__ __device__ __forceinline__ constexpr int pair_b(int p) {
    constexpr int t[8] = {6, 7, 8, 9, 10, 11, 13, 15}; return t[p];
}
// For each ic, the 6 pairs whose union-connectivity contains ic (exactly 6 each).
// constexpr so acc[pair_of(ic,j)] resolves at COMPILE TIME (acc stays in regs).
__host__ __device__ __forceinline__ constexpr int pair_of(int ic, int j) {
    constexpr int t[6][6] = {
        {0, 3, 4, 5, 6, 7},
        {0, 1, 4, 5, 6, 7},
        {0, 1, 2, 5, 6, 7},
        {0, 1, 2, 3, 6, 7},
        {1, 2, 3, 4, 6, 7},
        {2, 3, 4, 5, 6, 7}};
    return t[ic][j];
}

extern __shared__ unsigned char smem_raw[];

__global__ __launch_bounds__(256, 2)
void c3_kernel(const float* __restrict__ x, const float* __restrict__ w,
               const float* __restrict__ bias, float* __restrict__ out)
{
    u64* sW  = (u64*)smem_raw;                 // [ic][j][ky][kx] packed (w_a, w_b)
    u64* sin = (u64*)(smem_raw + SW_BYTES);    // [ic][col][row] duplicated (v, v)

    const int tid = threadIdx.x;
    const int tx = tid & 31, ty = tid >> 5;
    const int gx0 = blockIdx.x * TW, gy0 = blockIdx.y * TH;
    const int b = blockIdx.z;

    // ---- Stage packed weights: masked + oc-paired ----
    for (int i = tid; i < NW; i += 256) {
        int kx = i % 5; int t = i / 5;
        int ky = t % 5;  t /= 5;
        int j  = t % 6;  int ic = t / 6;
        int pr = pair_of(ic, j);
        int a  = pair_a(pr), bo = pair_b(pr);
        float wa = ((conn_bits(a)  >> ic) & 1u) ? w[((a  * IC + ic) * 5 + ky) * 5 + kx] : 0.f;
        float wb = ((conn_bits(bo) >> ic) & 1u) ? w[((bo * IC + ic) * 5 + ky) * 5 + kx] : 0.f;
        sW[i] = pack2(wa, wb);
    }

    // ---- Stage input tile, transposed [ic][col][row], values duplicated (v,v) ----
    // gx contiguous in i -> coalesced LDG.
    for (int i = tid; i < IC * TROWS * TCOLS; i += 256) {
        int c  = i % TCOLS;
        int t  = i / TCOLS;
        int r  = t % TROWS;
        int ic = t / TROWS;
        int gx = gx0 + c, gy = gy0 + r;
        float v = 0.f;
        if (gx < HW && gy < HW)
            v = x[(((size_t)b * IC + ic) * HW + gy) * HW + gx];
        sin[(ic * TCOLS + c) * RPITCH + r] = pack2(v, v);
    }
    __syncthreads();

    const int row0 = ty * RPT;

    u64 acc[8][RPT];
    #pragma unroll
    for (int p = 0; p < 8; ++p)
        #pragma unroll
        for (int r = 0; r < RPT; ++r) acc[p][r] = 0ULL;

    #pragma unroll
    for (int ic = 0; ic < IC; ++ic) {
        const u64* colp = &sin[(ic * TCOLS + tx) * RPITCH + row0];
        const u64* wp   = &sW[ic * 150];
        #pragma unroll 1                       // rolled kx: ~16 KB body, fits L1.5 I$
        for (int kx = 0; kx < 5; ++kx) {
            u64 p[RPT + 4];
            #pragma unroll
            for (int t = 0; t < RPT + 4; ++t) p[t] = colp[kx * RPITCH + t];

            #pragma unroll
            for (int j = 0; j < 6; ++j) {
                const int pr = pair_of(ic, j);     // compile-time constant (ic, j unrolled)
                #pragma unroll
                for (int ky = 0; ky < 5; ++ky) {
                    u64 w2 = wp[(j * 5 + ky) * 5 + kx];
                    #pragma unroll
                    for (int r = 0; r < RPT; ++r)
                        acc[pr][r] = ffma2(p[r + ky], w2, acc[pr][r]);
                }
            }
        }
    }

    // ---- Epilogue: unpack pairs, add bias, store (coalesced across lanes) ----
    const int ox = gx0 + tx;
    if (ox < OHW) {
        #pragma unroll
        for (int pr = 0; pr < 8; ++pr) {
            const int a = pair_a(pr), bo = pair_b(pr);
            const float ba = __ldg(&bias[a]);
            const float bb = __ldg(&bias[bo]);
            float* oa = out + ((size_t)b * OC + a)  * OHW * OHW + ox;
            float* ob = out + ((size_t)b * OC + bo) * OHW * OHW + ox;
            #pragma unroll
            for (int r = 0; r < RPT; ++r) {
                int oy = gy0 + row0 + r;
                if (oy < OHW) {
                    float2 f = unpack2(acc[pr][r]);
                    oa[(size_t)oy * OHW] = f.x + ba;
                    ob[(size_t)oy * OHW] = f.y + bb;
                }
            }
        }
    }
}

extern "C" void kernel_launch(void* const* d_in, const int* in_sizes, int n_in,
                              void* d_out, int out_size)
{
    const float* x    = (const float*)d_in[0];
    const float* w    = (const float*)d_in[1];
    const float* bias = (const float*)d_in[2];
    float* out = (float*)d_out;

    cudaFuncSetAttribute(c3_kernel, cudaFuncAttributeMaxDynamicSharedMemorySize, SMEM_TOTAL);

    dim3 grid((OHW + TW - 1) / TW, (OHW + TH - 1) / TH, 32);   // 16 x 16 x 32
    c3_kernel<<<grid, 256, SMEM_TOTAL>>>(x, w, bias, out);
}